// round 15
// baseline (speedup 1.0000x reference)
#include <cuda_runtime.h>
#include <cuda_fp16.h>
#include <math.h>
#include <stdint.h>

// ---------------- problem constants ----------------
#define T_TOK    16384
#define D_DIM    2048
#define E_EXP    64
#define TOK_TILE 128
#define NPAIR    (T_TOK / TOK_TILE)   // 128 token tiles
#define KSPLIT   2
#define KSLICE   (D_DIM / KSPLIT)     // 1024
#define NBLK     (NPAIR * KSPLIT)     // 256 CTAs
#define KC       32
#define NCH      (KSLICE / KC)        // 32
#define NSTAGE   3

// smem per stage: fp16 tiles, row stride 80B (64B data + 16B pad, conflict-free ldmatrix)
#define RS    80
#define A_HI  0
#define A_LO  10240                   // 128*80
#define B_HI  20480
#define B_LO  25600
#define STG   30720
#define DYN_BYTES (NSTAGE * STG)      // 92160 -> 2 CTAs/SM = 184KB

#define PROW 66

__device__ float g_plog[(size_t)NBLK * TOK_TILE * E_EXP];  // 8MB partial logits
__device__ unsigned int g_pair_cnt[NPAIR];
__device__ float g_partial[NPAIR * E_EXP];
__device__ unsigned int g_cnt = 0;

// ---------------- helpers ----------------
__device__ __forceinline__ uint32_t s2u(const void* p) {
    uint32_t a;
    asm("{ .reg .u64 t; cvta.to.shared.u64 t, %1; cvt.u32.u64 %0, t; }" : "=r"(a) : "l"(p));
    return a;
}

#define MBAR_INIT(a, n) asm volatile("mbarrier.init.shared.b64 [%0], %1;" :: "r"(a), "r"(n) : "memory")
#define MBAR_ARRIVE(a)  asm volatile("mbarrier.arrive.release.cta.shared::cta.b64 _, [%0];" :: "r"(a) : "memory")
#define MBAR_WAIT(a, ph) do {                                                          \
    uint32_t _m = (a), _p = (ph), _d;                                                  \
    asm volatile("{ .reg .pred p; mbarrier.try_wait.parity.acquire.cta.shared::cta.b64 p, [%1], %2; selp.b32 %0,1,0,p; }" \
        : "=r"(_d) : "r"(_m), "r"(_p) : "memory");                                     \
    if (!_d) {                                                                         \
        asm volatile("{ .reg .pred P1; WL_%=: mbarrier.try_wait.parity.acquire.cta.shared::cta.b64 P1, [%0], %1, 0x989680;\n\t" \
            "@P1 bra.uni WD_%=; bra.uni WL_%=; WD_%=: }" :: "r"(_m), "r"(_p) : "memory"); \
    } } while (0)

__device__ __forceinline__ void ldsm4(uint32_t* r, uint32_t addr) {
    asm volatile("ldmatrix.sync.aligned.m8n8.x4.shared.b16 {%0,%1,%2,%3}, [%4];"
        : "=r"(r[0]), "=r"(r[1]), "=r"(r[2]), "=r"(r[3]) : "r"(addr));
}

__device__ __forceinline__ void mma16816(float* c, const uint32_t* a, uint32_t b0, uint32_t b1) {
    asm volatile("mma.sync.aligned.m16n8k16.row.col.f32.f16.f16.f32 "
        "{%0,%1,%2,%3}, {%4,%5,%6,%7}, {%8,%9}, {%0,%1,%2,%3};"
        : "+f"(c[0]), "+f"(c[1]), "+f"(c[2]), "+f"(c[3])
        : "r"(a[0]), "r"(a[1]), "r"(a[2]), "r"(a[3]), "r"(b0), "r"(b1));
}

// split one float4 into fp16 hi/lo pairs and store (8B each) to smem
__device__ __forceinline__ void split_sts(float4 v, uint32_t ahi, uint32_t alo) {
    __half2 h0 = __floats2half2_rn(v.x, v.y);
    __half2 h1 = __floats2half2_rn(v.z, v.w);
    float2 f0 = __half22float2(h0);
    float2 f1 = __half22float2(h1);
    __half2 l0 = __floats2half2_rn(v.x - f0.x, v.y - f0.y);
    __half2 l1 = __floats2half2_rn(v.z - f1.x, v.w - f1.y);
    uint32_t u0 = *reinterpret_cast<uint32_t*>(&h0);
    uint32_t u1 = *reinterpret_cast<uint32_t*>(&h1);
    uint32_t w0 = *reinterpret_cast<uint32_t*>(&l0);
    uint32_t w1 = *reinterpret_cast<uint32_t*>(&l1);
    asm volatile("st.shared.v2.u32 [%0], {%1,%2};" :: "r"(ahi), "r"(u0), "r"(u1) : "memory");
    asm volatile("st.shared.v2.u32 [%0], {%1,%2};" :: "r"(alo), "r"(w0), "r"(w1) : "memory");
}

// ---------------- main kernel ----------------
__global__ __launch_bounds__(256, 2)
void router_hmma(const float* __restrict__ x, const float* __restrict__ W,
                 float* __restrict__ out, int out_size)
{
    extern __shared__ __align__(16) char dsm[];
    __shared__ __align__(8) uint64_t s_st[NSTAGE];  // stage full (stored)
    __shared__ __align__(8) uint64_t s_rd[NSTAGE];  // stage reads done
    const uint32_t base = s2u(dsm);

    const int tid  = threadIdx.x;
    const int lane = tid & 31;
    const int wid  = tid >> 5;
    const int wm   = wid & 3;
    const int wn   = wid >> 2;
    const int tile   = blockIdx.x & (NPAIR - 1);
    const int kslice = blockIdx.x >> 7;
    const int tok_base = tile * TOK_TILE;
    const int kbase = kslice * KSLICE;

    uint32_t stb[NSTAGE], rdb[NSTAGE];
#pragma unroll
    for (int s = 0; s < NSTAGE; s++) { stb[s] = s2u(&s_st[s]); rdb[s] = s2u(&s_rd[s]); }
    if (tid == 0) {
#pragma unroll
        for (int s = 0; s < NSTAGE; s++) { MBAR_INIT(stb[s], 256); MBAR_INIT(rdb[s], 256); }
    }
    __syncthreads();

    // loader assignment: A 128x8 float4 -> 4/thread, B 64x8 -> 2/thread
    const int lrow = tid >> 3;
    const int lq   = tid & 7;
    const float* gA[4];
    const float* gB[2];
#pragma unroll
    for (int j = 0; j < 4; j++)
        gA[j] = x + (size_t)(tok_base + lrow + 32 * j) * D_DIM + kbase + lq * 4;
#pragma unroll
    for (int j = 0; j < 2; j++)
        gB[j] = W + (size_t)(lrow + 32 * j) * D_DIM + kbase + lq * 4;

    uint32_t sAd[4], sBd[2];
#pragma unroll
    for (int j = 0; j < 4; j++) sAd[j] = base + (lrow + 32 * j) * RS + lq * 8;
#pragma unroll
    for (int j = 0; j < 2; j++) sBd[j] = base + (lrow + 32 * j) * RS + lq * 8;

    float4 va[4], vb[2];

    uint32_t a_addr[2], b_addr[2];
#pragma unroll
    for (int mi = 0; mi < 2; mi++) {
        int row = wm * 32 + mi * 16 + (lane & 15);
        int word = lane >> 4;
        a_addr[mi] = base + row * RS + word * 16;
    }
#pragma unroll
    for (int g = 0; g < 2; g++) {
        int row = wn * 32 + g * 16 + (lane & 7) + ((lane & 16) ? 8 : 0);
        int word = (lane >> 3) & 1;
        b_addr[g] = base + row * RS + word * 16;
    }

    float c[2][4][4];
#pragma unroll
    for (int mi = 0; mi < 2; mi++)
#pragma unroll
        for (int nj = 0; nj < 4; nj++)
#pragma unroll
            for (int r = 0; r < 4; r++) c[mi][nj][r] = 0.0f;

    // ---- prologue: chunk0 -> stage0 (+arrive st0), chunk1 -> regs ----
#pragma unroll
    for (int j = 0; j < 4; j++) va[j] = *reinterpret_cast<const float4*>(gA[j]);
#pragma unroll
    for (int j = 0; j < 2; j++) vb[j] = *reinterpret_cast<const float4*>(gB[j]);
#pragma unroll
    for (int j = 0; j < 4; j++) split_sts(va[j], sAd[j] + A_HI, sAd[j] + A_LO);
#pragma unroll
    for (int j = 0; j < 2; j++) split_sts(vb[j], sBd[j] + B_HI, sBd[j] + B_LO);
    MBAR_ARRIVE(stb[0]);
#pragma unroll
    for (int j = 0; j < 4; j++) va[j] = *reinterpret_cast<const float4*>(gA[j] + KC);
#pragma unroll
    for (int j = 0; j < 2; j++) vb[j] = *reinterpret_cast<const float4*>(gB[j] + KC);

    // CHUNK body: SB/SN are compile-time stage indices.
#define CHUNK(CH_, SB_, SN_, STPAR_, DO_RDWAIT_, RDPAR_, DO_STS_, DO_LDG_) do {         \
        const uint32_t sbb = base + (SB_) * STG;                                        \
        MBAR_WAIT(stb[SB_], (STPAR_));                                                  \
        _Pragma("unroll")                                                               \
        for (int ks = 0; ks < 2; ks++) {                                                \
            uint32_t ah[2][4], al[2][4], bh[2][4], bl[2][4];                            \
            _Pragma("unroll")                                                           \
            for (int mi = 0; mi < 2; mi++) {                                            \
                ldsm4(ah[mi], a_addr[mi] + (SB_) * STG + A_HI + ks * 32);               \
                ldsm4(al[mi], a_addr[mi] + (SB_) * STG + A_LO + ks * 32);               \
            }                                                                           \
            _Pragma("unroll")                                                           \
            for (int g2 = 0; g2 < 2; g2++) {                                            \
                ldsm4(bh[g2], b_addr[g2] + (SB_) * STG + B_HI + ks * 32);               \
                ldsm4(bl[g2], b_addr[g2] + (SB_) * STG + B_LO + ks * 32);               \
            }                                                                           \
            _Pragma("unroll")                                                           \
            for (int mi = 0; mi < 2; mi++)                                              \
                _Pragma("unroll")                                                       \
                for (int nj = 0; nj < 4; nj++) {                                        \
                    uint32_t b0 = bh[nj >> 1][(nj & 1) * 2];                            \
                    uint32_t b1 = bh[nj >> 1][(nj & 1) * 2 + 1];                        \
                    uint32_t l0 = bl[nj >> 1][(nj & 1) * 2];                            \
                    uint32_t l1 = bl[nj >> 1][(nj & 1) * 2 + 1];                        \
                    mma16816(c[mi][nj], ah[mi], b0, b1);                                \
                    mma16816(c[mi][nj], ah[mi], l0, l1);                                \
                    mma16816(c[mi][nj], al[mi], b0, b1);                                \
                }                                                                       \
        }                                                                               \
        if (DO_STS_) {                                                                  \
            if (DO_RDWAIT_) MBAR_WAIT(rdb[SN_], (RDPAR_));                              \
            const uint32_t ssb = (uint32_t)((SN_) * STG);                               \
            _Pragma("unroll")                                                           \
            for (int j = 0; j < 4; j++) split_sts(va[j], sAd[j] + ssb + A_HI, sAd[j] + ssb + A_LO); \
            _Pragma("unroll")                                                           \
            for (int j = 0; j < 2; j++) split_sts(vb[j], sBd[j] + ssb + B_HI, sBd[j] + ssb + B_LO); \
            MBAR_ARRIVE(stb[SN_]);                                                      \
        }                                                                               \
        if (DO_LDG_) {                                                                  \
            const int k0 = ((CH_) + 2) * KC;                                            \
            _Pragma("unroll")                                                           \
            for (int j = 0; j < 4; j++) va[j] = *reinterpret_cast<const float4*>(gA[j] + k0); \
            _Pragma("unroll")                                                           \
            for (int j = 0; j < 2; j++) vb[j] = *reinterpret_cast<const float4*>(gB[j] + k0); \
        }                                                                               \
        MBAR_ARRIVE(rdb[SB_]);                                                          \
        (void)sbb;                                                                      \
    } while (0)

    // groups of 3 chunks; NCH=32 -> 10 full groups (ch 0..29) + tail ch30, ch31
    for (int g = 0; g < 10; g++) {
        const int ch = 3 * g;
        const uint32_t p  = (uint32_t)(g & 1);
        const uint32_t pm = (uint32_t)((g - 1) & 1);
        const bool w = (g >= 1);
        CHUNK(ch + 0, 0, 1, p, w, pm, true, true);
        CHUNK(ch + 1, 1, 2, p, w, pm, true, true);
        CHUNK(ch + 2, 2, 0, p, true, p, true, true);
    }
    // tail: g=10 -> ch30 (stage0), ch31 (stage1)
    CHUNK(30, 0, 1, 0u, true, 1u, true, false);
    CHUNK(31, 1, 2, 0u, false, 0u, false, false);
#undef CHUNK

    // ---------------- write partial logits to global ----------------
    {
        float* pb = g_plog + (size_t)(tile * KSPLIT + kslice) * (TOK_TILE * E_EXP);
#pragma unroll
        for (int mi = 0; mi < 2; mi++) {
            int r0 = wm * 32 + mi * 16 + (lane >> 2);
#pragma unroll
            for (int nj = 0; nj < 4; nj++) {
                int col = wn * 32 + nj * 8 + (lane & 3) * 2;
                *reinterpret_cast<float2*>(&pb[r0 * E_EXP + col])       = make_float2(c[mi][nj][0], c[mi][nj][1]);
                *reinterpret_cast<float2*>(&pb[(r0 + 8) * E_EXP + col]) = make_float2(c[mi][nj][2], c[mi][nj][3]);
            }
        }
    }
    __threadfence();
    __syncthreads();

    // pair election: second finisher combines + runs epilogue
    __shared__ unsigned int s_old;
    if (tid == 0) s_old = atomicAdd(&g_pair_cnt[tile], 1u);
    __syncthreads();
    if (s_old == 0) return;
    if (tid == 0) g_pair_cnt[tile] = 0;
    __threadfence();

    // ---------------- combine partials (deterministic order p0+p1) ----------------
    float (*probs)[PROW] = reinterpret_cast<float(*)[PROW]>(dsm);
    float* rZ = reinterpret_cast<float*>(dsm) + TOK_TILE * PROW;
    {
        const float* p0 = g_plog + (size_t)(tile * KSPLIT + 0) * (TOK_TILE * E_EXP);
        const float* p1 = g_plog + (size_t)(tile * KSPLIT + 1) * (TOK_TILE * E_EXP);
#pragma unroll
        for (int j = 0; j < 16; j++) {
            int i = tid + 256 * j;
            int t = i >> 5;
            int e = (i & 31) * 2;
            float2 a0 = *reinterpret_cast<const float2*>(&p0[t * E_EXP + e]);
            float2 a1 = *reinterpret_cast<const float2*>(&p1[t * E_EXP + e]);
            probs[t][e]     = a0.x + a1.x;
            probs[t][e + 1] = a0.y + a1.y;
        }
    }
    __syncthreads();

    const int woff = (out_size - 1) / 2;

    if (tid < TOK_TILE) {
        const int t = tid;
        float v1 = -INFINITY, v2 = -INFINITY;
        int i1 = 0, i2 = 0;
#pragma unroll 8
        for (int e = 0; e < E_EXP; e++) {
            float l = probs[t][e];
            if (l > v1)      { v2 = v1; i2 = i1; v1 = l; i1 = e; }
            else if (l > v2) { v2 = l;  i2 = e; }
        }
        float ssum = 0.0f;
#pragma unroll 8
        for (int e = 0; e < E_EXP; e++) {
            float p = expf(probs[t][e] - v1);
            probs[t][e] = p;
            ssum += p;
        }
        rZ[t] = 1.0f / ssum;

        float e2 = expf(v2 - v1);
        float inv = 1.0f / (1.0f + e2);
        int gt = tok_base + t;
        out[2 * gt]            = (float)i1;
        out[2 * gt + 1]        = (float)i2;
        out[woff + 2 * gt]     = inv;
        out[woff + 2 * gt + 1] = e2 * inv;
    }
    __syncthreads();

    if (tid < E_EXP) {
        float u = 0.0f;
        for (int t = 0; t < TOK_TILE; t++)
            u += probs[t][tid] * rZ[t];
        g_partial[tile * E_EXP + tid] = u;
    }

    // ---------------- fused aux-loss reduction (last combiner) ----------------
    __threadfence();
    __syncthreads();
    __shared__ unsigned int s_last;
    if (tid == 0) s_last = (atomicAdd(&g_cnt, 1u) == (unsigned)(NPAIR - 1));
    __syncthreads();
    if (s_last) {
        __threadfence();
        float (*red)[E_EXP] = reinterpret_cast<float(*)[E_EXP]>(dsm);
        float* sq = reinterpret_cast<float*>(dsm) + 4 * E_EXP;
        const int e = tid & 63;
        const int part = tid >> 6;
        float u = 0.0f;
#pragma unroll 8
        for (int b = part * 32; b < part * 32 + 32; b++)
            u += g_partial[b * E_EXP + e];
        red[part][e] = u;
        __syncthreads();
        if (tid < E_EXP) {
            float s2 = (red[0][tid] + red[1][tid]) + (red[2][tid] + red[3][tid]);
            s2 *= (1.0f / (float)T_TOK);
            float d = s2 - 1.0f / (float)E_EXP;
            sq[tid] = d * d;
        }
        __syncthreads();
        if (tid < 32) {
            float s2 = sq[tid] + sq[tid + 32];
#pragma unroll
            for (int o = 16; o > 0; o >>= 1)
                s2 += __shfl_down_sync(0xFFFFFFFFu, s2, o);
            if (tid == 0) {
                out[out_size - 1] = s2;
                g_cnt = 0;
            }
        }
    }
}

extern "C" void kernel_launch(void* const* d_in, const int* in_sizes, int n_in,
                              void* d_out, int out_size)
{
    const float* x = (const float*)d_in[0];
    const float* W = (const float*)d_in[1];
    float* out = (float*)d_out;

    cudaFuncSetAttribute(router_hmma, cudaFuncAttributeMaxDynamicSharedMemorySize, DYN_BYTES);
    router_hmma<<<NBLK, 256, DYN_BYTES>>>(x, W, out, out_size);
}

// round 16
// speedup vs baseline: 1.1416x; 1.1416x over previous
#include <cuda_runtime.h>
#include <cuda_fp16.h>
#include <math.h>
#include <stdint.h>

// ---------------- problem constants ----------------
#define T_TOK    16384
#define D_DIM    2048
#define E_EXP    64
#define TOK_TILE 128
#define NPAIR    (T_TOK / TOK_TILE)   // 128 token tiles
#define KSPLIT   2                    // split-K factor
#define KSLICE   (D_DIM / KSPLIT)     // 1024 per CTA
#define NBLK     (NPAIR * KSPLIT)     // 256 CTAs
#define KC       32                   // K per chunk
#define NCH      (KSLICE / KC)        // 32

// smem per stage: fp16 tiles, row stride 80B (64B data + 16B pad, conflict-free ldmatrix)
#define RS    80
#define A_HI  0
#define A_LO  10240                   // 128*80
#define B_HI  20480
#define B_LO  25600                   // +64*80
#define STG   30720
#define DYN_BYTES (2 * STG)           // 61440 -> 2 CTAs/SM = 120KB

#define PROW 66

__device__ float g_plog[(size_t)NBLK * TOK_TILE * E_EXP];  // 8MB partial logits
__device__ unsigned int g_pair_cnt[NPAIR];
__device__ float g_partial[NPAIR * E_EXP];
__device__ unsigned int g_cnt = 0;

// ---------------- helpers ----------------
__device__ __forceinline__ uint32_t s2u(const void* p) {
    uint32_t a;
    asm("{ .reg .u64 t; cvta.to.shared.u64 t, %1; cvt.u32.u64 %0, t; }" : "=r"(a) : "l"(p));
    return a;
}

__device__ __forceinline__ void ldsm4(uint32_t* r, uint32_t addr) {
    asm volatile("ldmatrix.sync.aligned.m8n8.x4.shared.b16 {%0,%1,%2,%3}, [%4];"
        : "=r"(r[0]), "=r"(r[1]), "=r"(r[2]), "=r"(r[3]) : "r"(addr));
}

// NON-volatile: pure register op; data deps ("+f") carry all ordering.
// ptxas is free to interleave these with the (volatile) STS and the LDGs,
// software-pipelining the chunk body.
__device__ __forceinline__ void mma16816(float* c, const uint32_t* a, uint32_t b0, uint32_t b1) {
    asm("mma.sync.aligned.m16n8k16.row.col.f32.f16.f16.f32 "
        "{%0,%1,%2,%3}, {%4,%5,%6,%7}, {%8,%9}, {%0,%1,%2,%3};"
        : "+f"(c[0]), "+f"(c[1]), "+f"(c[2]), "+f"(c[3])
        : "r"(a[0]), "r"(a[1]), "r"(a[2]), "r"(a[3]), "r"(b0), "r"(b1));
}

// split one float4 into fp16 hi/lo pairs and store (8B each) to smem
__device__ __forceinline__ void split_sts(float4 v, uint32_t ahi, uint32_t alo) {
    __half2 h0 = __floats2half2_rn(v.x, v.y);
    __half2 h1 = __floats2half2_rn(v.z, v.w);
    float2 f0 = __half22float2(h0);
    float2 f1 = __half22float2(h1);
    __half2 l0 = __floats2half2_rn(v.x - f0.x, v.y - f0.y);
    __half2 l1 = __floats2half2_rn(v.z - f1.x, v.w - f1.y);
    uint32_t u0 = *reinterpret_cast<uint32_t*>(&h0);
    uint32_t u1 = *reinterpret_cast<uint32_t*>(&h1);
    uint32_t w0 = *reinterpret_cast<uint32_t*>(&l0);
    uint32_t w1 = *reinterpret_cast<uint32_t*>(&l1);
    asm volatile("st.shared.v2.u32 [%0], {%1,%2};" :: "r"(ahi), "r"(u0), "r"(u1) : "memory");
    asm volatile("st.shared.v2.u32 [%0], {%1,%2};" :: "r"(alo), "r"(w0), "r"(w1) : "memory");
}

// ---------------- main kernel ----------------
__global__ __launch_bounds__(256, 2)
void router_hmma(const float* __restrict__ x, const float* __restrict__ W,
                 float* __restrict__ out, int out_size)
{
    extern __shared__ __align__(16) char dsm[];
    const uint32_t base = s2u(dsm);

    const int tid  = threadIdx.x;
    const int lane = tid & 31;
    const int wid  = tid >> 5;
    const int wm   = wid & 3;    // m block (32 rows)
    const int wn   = wid >> 2;   // n block (32 cols)
    const int tile   = blockIdx.x & (NPAIR - 1);
    const int kslice = blockIdx.x >> 7;
    const int tok_base = tile * TOK_TILE;
    const int kbase = kslice * KSLICE;

    // loader assignment: A 128x8 float4 -> 4/thread, B 64x8 -> 2/thread
    const int lrow = tid >> 3;
    const int lq   = tid & 7;
    const float* gA[4];
    const float* gB[2];
#pragma unroll
    for (int j = 0; j < 4; j++)
        gA[j] = x + (size_t)(tok_base + lrow + 32 * j) * D_DIM + kbase + lq * 4;
#pragma unroll
    for (int j = 0; j < 2; j++)
        gB[j] = W + (size_t)(lrow + 32 * j) * D_DIM + kbase + lq * 4;

    uint32_t sAd[4], sBd[2];
#pragma unroll
    for (int j = 0; j < 4; j++) sAd[j] = base + (lrow + 32 * j) * RS + lq * 8;
#pragma unroll
    for (int j = 0; j < 2; j++) sBd[j] = base + (lrow + 32 * j) * RS + lq * 8;

    float4 va[4], vb[2];

    // ldmatrix base addresses (stage 0, ks=0); +ks*32, +STG per stage
    uint32_t a_addr[2], b_addr[2];
#pragma unroll
    for (int mi = 0; mi < 2; mi++) {
        int row = wm * 32 + mi * 16 + (lane & 15);
        int word = lane >> 4;
        a_addr[mi] = base + row * RS + word * 16;
    }
#pragma unroll
    for (int g = 0; g < 2; g++) {
        int row = wn * 32 + g * 16 + (lane & 7) + ((lane & 16) ? 8 : 0);
        int word = (lane >> 3) & 1;
        b_addr[g] = base + row * RS + word * 16;
    }

    float c[2][4][4];
#pragma unroll
    for (int mi = 0; mi < 2; mi++)
#pragma unroll
        for (int nj = 0; nj < 4; nj++)
#pragma unroll
            for (int r = 0; r < 4; r++) c[mi][nj][r] = 0.0f;

    // ---- prologue: chunk0 load+store, chunk1 load ----
#pragma unroll
    for (int j = 0; j < 4; j++) va[j] = *reinterpret_cast<const float4*>(gA[j]);
#pragma unroll
    for (int j = 0; j < 2; j++) vb[j] = *reinterpret_cast<const float4*>(gB[j]);
#pragma unroll
    for (int j = 0; j < 4; j++) split_sts(va[j], sAd[j] + A_HI, sAd[j] + A_LO);
#pragma unroll
    for (int j = 0; j < 2; j++) split_sts(vb[j], sBd[j] + B_HI, sBd[j] + B_LO);
#pragma unroll
    for (int j = 0; j < 4; j++) va[j] = *reinterpret_cast<const float4*>(gA[j] + KC);
#pragma unroll
    for (int j = 0; j < 2; j++) vb[j] = *reinterpret_cast<const float4*>(gB[j] + KC);
    __syncthreads();

    for (int ch = 0; ch < NCH; ch++) {
        const uint32_t sb = (ch & 1) ? STG : 0;

        // compute: frags loaded per k-step (register budget for 2 CTAs/SM)
#pragma unroll
        for (int ks = 0; ks < 2; ks++) {
            uint32_t ah[2][4], al[2][4], bh[2][4], bl[2][4];
#pragma unroll
            for (int mi = 0; mi < 2; mi++) {
                ldsm4(ah[mi], a_addr[mi] + sb + A_HI + ks * 32);
                ldsm4(al[mi], a_addr[mi] + sb + A_LO + ks * 32);
            }
#pragma unroll
            for (int g = 0; g < 2; g++) {
                ldsm4(bh[g], b_addr[g] + sb + B_HI + ks * 32);
                ldsm4(bl[g], b_addr[g] + sb + B_LO + ks * 32);
            }
#pragma unroll
            for (int mi = 0; mi < 2; mi++)
#pragma unroll
                for (int nj = 0; nj < 4; nj++) {
                    uint32_t b0 = bh[nj >> 1][(nj & 1) * 2];
                    uint32_t b1 = bh[nj >> 1][(nj & 1) * 2 + 1];
                    uint32_t l0 = bl[nj >> 1][(nj & 1) * 2];
                    uint32_t l1 = bl[nj >> 1][(nj & 1) * 2 + 1];
                    mma16816(c[mi][nj], ah[mi], b0, b1);  // hh
                    mma16816(c[mi][nj], ah[mi], l0, l1);  // hl
                    mma16816(c[mi][nj], al[mi], b0, b1);  // lh
                }
        }

        // stage ch+1 store, chunk ch+2 load
        if (ch + 1 < NCH) {
            const uint32_t ss = (ch & 1) ? 0 : STG;
#pragma unroll
            for (int j = 0; j < 4; j++) split_sts(va[j], sAd[j] + ss + A_HI, sAd[j] + ss + A_LO);
#pragma unroll
            for (int j = 0; j < 2; j++) split_sts(vb[j], sBd[j] + ss + B_HI, sBd[j] + ss + B_LO);
            if (ch + 2 < NCH) {
                const int k0 = (ch + 2) * KC;
#pragma unroll
                for (int j = 0; j < 4; j++) va[j] = *reinterpret_cast<const float4*>(gA[j] + k0);
#pragma unroll
                for (int j = 0; j < 2; j++) vb[j] = *reinterpret_cast<const float4*>(gB[j] + k0);
            }
        }
        __syncthreads();
    }

    // ---------------- write partial logits to global ----------------
    {
        float* pb = g_plog + (size_t)(tile * KSPLIT + kslice) * (TOK_TILE * E_EXP);
#pragma unroll
        for (int mi = 0; mi < 2; mi++) {
            int r0 = wm * 32 + mi * 16 + (lane >> 2);
#pragma unroll
            for (int nj = 0; nj < 4; nj++) {
                int col = wn * 32 + nj * 8 + (lane & 3) * 2;
                *reinterpret_cast<float2*>(&pb[r0 * E_EXP + col])       = make_float2(c[mi][nj][0], c[mi][nj][1]);
                *reinterpret_cast<float2*>(&pb[(r0 + 8) * E_EXP + col]) = make_float2(c[mi][nj][2], c[mi][nj][3]);
            }
        }
    }
    __threadfence();
    __syncthreads();

    // pair election: second finisher combines + runs epilogue
    __shared__ unsigned int s_old;
    if (tid == 0) s_old = atomicAdd(&g_pair_cnt[tile], 1u);
    __syncthreads();
    if (s_old == 0) return;                 // uniform per CTA
    if (tid == 0) g_pair_cnt[tile] = 0;     // reset for next graph replay
    __threadfence();

    // ---------------- combine partials (deterministic order p0+p1) ----------------
    float (*probs)[PROW] = reinterpret_cast<float(*)[PROW]>(dsm);
    float* rZ = reinterpret_cast<float*>(dsm) + TOK_TILE * PROW;
    {
        const float* p0 = g_plog + (size_t)(tile * KSPLIT + 0) * (TOK_TILE * E_EXP);
        const float* p1 = g_plog + (size_t)(tile * KSPLIT + 1) * (TOK_TILE * E_EXP);
#pragma unroll
        for (int j = 0; j < 16; j++) {
            int i = tid + 256 * j;          // float2 index, 4096 total
            int t = i >> 5;
            int e = (i & 31) * 2;
            float2 a0 = *reinterpret_cast<const float2*>(&p0[t * E_EXP + e]);
            float2 a1 = *reinterpret_cast<const float2*>(&p1[t * E_EXP + e]);
            probs[t][e]     = a0.x + a1.x;
            probs[t][e + 1] = a0.y + a1.y;
        }
    }
    __syncthreads();

    const int woff = (out_size - 1) / 2;

    if (tid < TOK_TILE) {
        const int t = tid;
        float v1 = -INFINITY, v2 = -INFINITY;
        int i1 = 0, i2 = 0;
#pragma unroll 8
        for (int e = 0; e < E_EXP; e++) {
            float l = probs[t][e];
            if (l > v1)      { v2 = v1; i2 = i1; v1 = l; i1 = e; }
            else if (l > v2) { v2 = l;  i2 = e; }
        }
        float ssum = 0.0f;
#pragma unroll 8
        for (int e = 0; e < E_EXP; e++) {
            float p = expf(probs[t][e] - v1);
            probs[t][e] = p;
            ssum += p;
        }
        rZ[t] = 1.0f / ssum;

        float e2 = expf(v2 - v1);
        float inv = 1.0f / (1.0f + e2);
        int gt = tok_base + t;
        out[2 * gt]            = (float)i1;
        out[2 * gt + 1]        = (float)i2;
        out[woff + 2 * gt]     = inv;
        out[woff + 2 * gt + 1] = e2 * inv;
    }
    __syncthreads();

    if (tid < E_EXP) {
        float u = 0.0f;
        for (int t = 0; t < TOK_TILE; t++)
            u += probs[t][tid] * rZ[t];
        g_partial[tile * E_EXP + tid] = u;
    }

    // ---------------- fused aux-loss reduction (last combiner) ----------------
    __threadfence();
    __syncthreads();
    __shared__ unsigned int s_last;
    if (tid == 0) s_last = (atomicAdd(&g_cnt, 1u) == (unsigned)(NPAIR - 1));
    __syncthreads();
    if (s_last) {
        __threadfence();
        float (*red)[E_EXP] = reinterpret_cast<float(*)[E_EXP]>(dsm);
        float* sq = reinterpret_cast<float*>(dsm) + 4 * E_EXP;
        const int e = tid & 63;
        const int part = tid >> 6;  // 0..3, 32 tiles each
        float u = 0.0f;
#pragma unroll 8
        for (int b = part * 32; b < part * 32 + 32; b++)
            u += g_partial[b * E_EXP + e];
        red[part][e] = u;
        __syncthreads();
        if (tid < E_EXP) {
            float s2 = (red[0][tid] + red[1][tid]) + (red[2][tid] + red[3][tid]);
            s2 *= (1.0f / (float)T_TOK);
            float d = s2 - 1.0f / (float)E_EXP;
            sq[tid] = d * d;
        }
        __syncthreads();
        if (tid < 32) {
            float s2 = sq[tid] + sq[tid + 32];
#pragma unroll
            for (int o = 16; o > 0; o >>= 1)
                s2 += __shfl_down_sync(0xFFFFFFFFu, s2, o);
            if (tid == 0) {
                out[out_size - 1] = s2;
                g_cnt = 0;  // reset for next graph replay
            }
        }
    }
}

extern "C" void kernel_launch(void* const* d_in, const int* in_sizes, int n_in,
                              void* d_out, int out_size)
{
    const float* x = (const float*)d_in[0];
    const float* W = (const float*)d_in[1];
    float* out = (float*)d_out;

    cudaFuncSetAttribute(router_hmma, cudaFuncAttributeMaxDynamicSharedMemorySize, DYN_BYTES);
    router_hmma<<<NBLK, 256, DYN_BYTES>>>(x, W, out, out_size);
}